// round 4
// baseline (speedup 1.0000x reference)
#include <cuda_runtime.h>

#define FS 4096
#define FT 4096
#define NPTS (FS * 8)
#define TPB 256
#define RTPB 128
#define HALF 2048
#define FWD_BLK 256
#define MRG_BLK 128

typedef unsigned long long u64;

// Scratch (allocation-free: __device__ globals)
__device__ float4 g_src_bc[FS];      // xyz, w = 0.5*|bc|^2
__device__ float4 g_tgt_bc[FT];      // xyz, w = 0.5*|bc|^2
__device__ float4 g_pts[NPTS];       // xyz, w = |pt|^2
__device__ float  g_be[2][NPTS][6];  // per-half top-6 e values (ascending)
__device__ int    g_bi[2][NPTS][6];  // per-half top-6 indices
__device__ float  g_mteh[2][NPTS];   // per-half target min-e
__device__ float  g_fwd_partial[FWD_BLK];
__device__ float  g_rev_partial[MRG_BLK];

// ---- packed f32x2 helpers (sm_103a) ---------------------------------------
__device__ __forceinline__ u64 pk2(float a, float b) {
    u64 r; asm("mov.b64 %0,{%1,%2};" : "=l"(r) : "f"(a), "f"(b)); return r;
}
__device__ __forceinline__ u64 fma2(u64 a, u64 b, u64 c) {
    u64 d; asm("fma.rn.f32x2 %0,%1,%2,%3;" : "=l"(d) : "l"(a), "l"(b), "l"(c)); return d;
}
__device__ __forceinline__ void upk2(u64 d, float& x, float& y) {
    asm("mov.b64 {%0,%1},%2;" : "=f"(x), "=f"(y) : "l"(d));
}

// ascending insert, strict < keeps earlier (lower-index) candidate on ties
__device__ __forceinline__ void try_insert(float e, int j, float be[6], int bi[6]) {
    if (e < be[5]) {
        be[5] = e; bi[5] = j;
        #pragma unroll
        for (int k = 5; k > 0; --k) {
            if (be[k] < be[k-1]) {
                float te = be[k]; be[k] = be[k-1]; be[k-1] = te;
                int   ti = bi[k]; bi[k] = bi[k-1]; bi[k-1] = ti;
            }
        }
    }
}

// Pack HALF candidates (pair-interleaved) from g[off..off+HALF) into smem.
__device__ __forceinline__ void load_packed_half(ulonglong2* s, const float4* g,
                                                 int off, int tid) {
    for (int t = tid; t < HALF/2; t += RTPB) {
        float4 a = g[off + 2*t], b = g[off + 2*t + 1];
        ulonglong2 u0, u1;
        u0.x = pk2(a.x, b.x); u0.y = pk2(a.y, b.y);
        u1.x = pk2(a.z, b.z); u1.y = pk2(a.w, b.w);
        s[2*t]   = u0;
        s[2*t+1] = u1;
    }
}

// ---------------------------------------------------------------------------
// Kernel 1: barycenters + sampled points
// ---------------------------------------------------------------------------
__global__ void prep_kernel(const float* __restrict__ sv, const int* __restrict__ sf,
                            const float* __restrict__ tv, const int* __restrict__ tf,
                            const float* __restrict__ r1u, const float* __restrict__ r2u) {
    int i = blockIdx.x * blockDim.x + threadIdx.x;
    if (i < FS) {
        int a = sf[3*i+0], b = sf[3*i+1], c = sf[3*i+2];
        float x = (sv[3*a+0] + sv[3*b+0] + sv[3*c+0]) * (1.0f/3.0f);
        float y = (sv[3*a+1] + sv[3*b+1] + sv[3*c+1]) * (1.0f/3.0f);
        float z = (sv[3*a+2] + sv[3*b+2] + sv[3*c+2]) * (1.0f/3.0f);
        g_src_bc[i] = make_float4(x, y, z, 0.5f*(x*x + y*y + z*z));
        int ta = tf[i], tb = tf[FT + i], tc = tf[2*FT + i];
        float tx = (tv[3*ta+0] + tv[3*tb+0] + tv[3*tc+0]) * (1.0f/3.0f);
        float ty = (tv[3*ta+1] + tv[3*tb+1] + tv[3*tc+1]) * (1.0f/3.0f);
        float tz = (tv[3*ta+2] + tv[3*tb+2] + tv[3*tc+2]) * (1.0f/3.0f);
        g_tgt_bc[i] = make_float4(tx, ty, tz, 0.5f*(tx*tx + ty*ty + tz*tz));
    }
    if (i < NPTS) {
        int f = i >> 3;
        int a = sf[3*f+0], b = sf[3*f+1], c = sf[3*f+2];
        float r1 = sqrtf(r1u[i]);
        float r2 = r2u[i];
        float w1 = 1.0f - r1;
        float w2 = r1 * (1.0f - r2);
        float w3 = r1 * r2;
        float x = w1*sv[3*a+0] + w2*sv[3*b+0] + w3*sv[3*c+0];
        float y = w1*sv[3*a+1] + w2*sv[3*b+1] + w3*sv[3*c+1];
        float z = w1*sv[3*a+2] + w2*sv[3*b+2] + w3*sv[3*c+2];
        g_pts[i] = make_float4(x, y, z, x*x + y*y + z*z);
    }
}

// ---------------------------------------------------------------------------
// Kernel 2: reverse target min — half the candidates per block, 2 pts/thread.
// grid 256: block = (point-group pg = b>>1) x (half h = b&1)
// ---------------------------------------------------------------------------
__global__ void rev_tgt_kernel() {
    __shared__ ulonglong2 s_pk[HALF];   // 32 KB
    int tid = threadIdx.x;
    int pg  = blockIdx.x >> 1;
    int h   = blockIdx.x & 1;
    load_packed_half(s_pk, g_tgt_bc, h * HALF, tid);
    __syncthreads();

    int i0 = pg * 256 + tid;
    int i1 = i0 + 128;
    float4 p0 = g_pts[i0], p1 = g_pts[i1];
    u64 ax = pk2(-p0.x, -p0.x), ay = pk2(-p0.y, -p0.y), az = pk2(-p0.z, -p0.z);
    u64 bx = pk2(-p1.x, -p1.x), by = pk2(-p1.y, -p1.y), bz = pk2(-p1.z, -p1.z);

    float m00 = 1e30f, m01 = 1e30f, m10 = 1e30f, m11 = 1e30f;
    #pragma unroll 4
    for (int t = 0; t < HALF/4; t++) {
        ulonglong2 A = s_pk[4*t+0], B = s_pk[4*t+1];
        ulonglong2 C = s_pk[4*t+2], D = s_pk[4*t+3];
        u64 d00 = fma2(ax, A.x, fma2(ay, A.y, fma2(az, B.x, B.y)));
        u64 d01 = fma2(ax, C.x, fma2(ay, C.y, fma2(az, D.x, D.y)));
        u64 d10 = fma2(bx, A.x, fma2(by, A.y, fma2(bz, B.x, B.y)));
        u64 d11 = fma2(bx, C.x, fma2(by, C.y, fma2(bz, D.x, D.y)));
        float e0, e1, e2, e3;
        upk2(d00, e0, e1); upk2(d01, e2, e3);
        m00 = fminf(m00, fminf(e0, e1));
        m01 = fminf(m01, fminf(e2, e3));
        upk2(d10, e0, e1); upk2(d11, e2, e3);
        m10 = fminf(m10, fminf(e0, e1));
        m11 = fminf(m11, fminf(e2, e3));
    }
    g_mteh[h][i0] = fminf(m00, m01);
    g_mteh[h][i1] = fminf(m10, m11);
}

// ---------------------------------------------------------------------------
// Kernel 3: reverse source partial top-6 — half candidates, 2 pts/thread.
// ---------------------------------------------------------------------------
__global__ void rev_src_kernel() {
    __shared__ ulonglong2 s_pk[HALF];   // 32 KB
    int tid = threadIdx.x;
    int pg  = blockIdx.x >> 1;
    int h   = blockIdx.x & 1;
    int jb  = h * HALF;
    load_packed_half(s_pk, g_src_bc, jb, tid);
    __syncthreads();

    int i0 = pg * 256 + tid;
    int i1 = i0 + 128;
    float4 p0 = g_pts[i0], p1 = g_pts[i1];
    u64 ax = pk2(-p0.x, -p0.x), ay = pk2(-p0.y, -p0.y), az = pk2(-p0.z, -p0.z);
    u64 bx = pk2(-p1.x, -p1.x), by = pk2(-p1.y, -p1.y), bz = pk2(-p1.z, -p1.z);

    float beA[6], beB[6]; int biA[6], biB[6];
    #pragma unroll
    for (int k = 0; k < 6; k++) {
        beA[k] = 1e30f; biA[k] = -1;
        beB[k] = 1e30f; biB[k] = -1;
    }

    for (int c = 0; c < HALF/8; c++) {        // 256 chunks of 8 candidates
        ulonglong2 A = s_pk[8*c+0], B = s_pk[8*c+1];
        ulonglong2 C = s_pk[8*c+2], D = s_pk[8*c+3];
        ulonglong2 E = s_pk[8*c+4], F = s_pk[8*c+5];
        ulonglong2 G = s_pk[8*c+6], H = s_pk[8*c+7];
        // point 0
        u64 d0 = fma2(ax, A.x, fma2(ay, A.y, fma2(az, B.x, B.y)));
        u64 d1 = fma2(ax, C.x, fma2(ay, C.y, fma2(az, D.x, D.y)));
        u64 d2 = fma2(ax, E.x, fma2(ay, E.y, fma2(az, F.x, F.y)));
        u64 d3 = fma2(ax, G.x, fma2(ay, G.y, fma2(az, H.x, H.y)));
        float e0,e1,e2,e3,e4,e5,e6,e7;
        upk2(d0,e0,e1); upk2(d1,e2,e3); upk2(d2,e4,e5); upk2(d3,e6,e7);
        float m = fminf(fminf(fminf(e0,e1), fminf(e2,e3)),
                        fminf(fminf(e4,e5), fminf(e6,e7)));
        if (m < beA[5]) {
            int j = jb + 8*c;
            try_insert(e0, j+0, beA, biA); try_insert(e1, j+1, beA, biA);
            try_insert(e2, j+2, beA, biA); try_insert(e3, j+3, beA, biA);
            try_insert(e4, j+4, beA, biA); try_insert(e5, j+5, beA, biA);
            try_insert(e6, j+6, beA, biA); try_insert(e7, j+7, beA, biA);
        }
        // point 1
        d0 = fma2(bx, A.x, fma2(by, A.y, fma2(bz, B.x, B.y)));
        d1 = fma2(bx, C.x, fma2(by, C.y, fma2(bz, D.x, D.y)));
        d2 = fma2(bx, E.x, fma2(by, E.y, fma2(bz, F.x, F.y)));
        d3 = fma2(bx, G.x, fma2(by, G.y, fma2(bz, H.x, H.y)));
        upk2(d0,e0,e1); upk2(d1,e2,e3); upk2(d2,e4,e5); upk2(d3,e6,e7);
        m = fminf(fminf(fminf(e0,e1), fminf(e2,e3)),
                  fminf(fminf(e4,e5), fminf(e6,e7)));
        if (m < beB[5]) {
            int j = jb + 8*c;
            try_insert(e0, j+0, beB, biB); try_insert(e1, j+1, beB, biB);
            try_insert(e2, j+2, beB, biB); try_insert(e3, j+3, beB, biB);
            try_insert(e4, j+4, beB, biB); try_insert(e5, j+5, beB, biB);
            try_insert(e6, j+6, beB, biB); try_insert(e7, j+7, beB, biB);
        }
    }
    #pragma unroll
    for (int k = 0; k < 6; k++) {
        g_be[h][i0][k] = beA[k];  g_bi[h][i0][k] = biA[k];
        g_be[h][i1][k] = beB[k];  g_bi[h][i1][k] = biB[k];
    }
}

// ---------------------------------------------------------------------------
// Kernel 4: forward loss (16 lanes per source face, 256 blocks)
// ---------------------------------------------------------------------------
__global__ void fwd_kernel(const float* __restrict__ probs) {
    extern __shared__ float4 s_tgt[];   // FT float4 = 64 KB
    int tid = threadIdx.x;
    for (int k = tid; k < FT; k += TPB) s_tgt[k] = g_tgt_bc[k];
    __syncthreads();

    int gid   = blockIdx.x * TPB + tid;   // 0..65535
    int face  = gid >> 4;
    int chunk = gid & 15;
    float4 p  = g_src_bc[face];           // p.w = 0.5*|p|^2

    float beste = 1e30f;
    #pragma unroll 8
    for (int t = 0; t < FT/16; t++) {
        float4 q = s_tgt[chunk + 16*t];
        float e = fmaf(-p.x, q.x, fmaf(-p.y, q.y, fmaf(-p.z, q.z, q.w)));
        beste = fminf(beste, e);
    }
    beste = fminf(beste, __shfl_xor_sync(0xffffffffu, beste, 1));
    beste = fminf(beste, __shfl_xor_sync(0xffffffffu, beste, 2));
    beste = fminf(beste, __shfl_xor_sync(0xffffffffu, beste, 4));
    beste = fminf(beste, __shfl_xor_sync(0xffffffffu, beste, 8));

    float contrib = 0.0f;
    if (chunk == 0) {
        float d = fmaxf(2.0f * (p.w + beste), 0.0f);
        contrib = probs[face] * d;
    }
    __shared__ float red[TPB];
    red[tid] = contrib;
    __syncthreads();
    #pragma unroll
    for (int s = TPB/2; s > 0; s >>= 1) {
        if (tid < s) red[tid] += red[tid + s];
        __syncthreads();
    }
    if (tid == 0) g_fwd_partial[blockIdx.x] = red[0];
}

// ---------------------------------------------------------------------------
// Kernel 5: merge halves, self-exclusion, per-point value, block reduce.
// ---------------------------------------------------------------------------
__global__ void merge_kernel(const float* __restrict__ probs) {
    int tid = threadIdx.x;
    int i   = blockIdx.x * TPB + tid;
    int sface = i >> 3;

    float beA[6], beB[6]; int biA[6], biB[6];
    #pragma unroll
    for (int k = 0; k < 6; k++) {
        beA[k] = g_be[0][i][k]; biA[k] = g_bi[0][i][k];
        beB[k] = g_be[1][i][k]; biB[k] = g_bi[1][i][k];
    }
    // merge two ascending 6-lists -> 6 smallest (tie -> half 0 = lower index)
    float me[6]; int mi[6];
    int a = 0, b = 0;
    #pragma unroll
    for (int k = 0; k < 6; k++) {
        float va = beA[a], vb = beB[b];
        bool tA = (va <= vb);
        me[k] = tA ? va : vb;
        mi[k] = tA ? biA[a] : biB[b];
        a += tA ? 1 : 0;
        b += tA ? 0 : 1;
    }

    float pw = g_pts[i].w;
    int selfpos = 6;
    #pragma unroll
    for (int k = 0; k < 6; k++) if (mi[k] == sface) selfpos = k;
    float s5 = 0.0f;
    #pragma unroll
    for (int k = 0; k < 6; k++) {
        bool inc = (k != selfpos) && (k < 5 || selfpos <= 5);
        if (inc) {
            float d = fmaxf(fmaf(2.0f, me[k], pw), 0.0f);
            s5 += probs[mi[k]] * d;
        }
    }
    float mte  = fminf(g_mteh[0][i], g_mteh[1][i]);
    float pp   = probs[sface];
    float mind = fmaxf(fmaf(2.0f, mte, pw), 0.0f);
    float val  = fmaf(pp, mind, (1.0f - pp) * (s5 * 0.2f));

    __shared__ float red[TPB];
    red[tid] = val;
    __syncthreads();
    #pragma unroll
    for (int s = TPB/2; s > 0; s >>= 1) {
        if (tid < s) red[tid] += red[tid + s];
        __syncthreads();
    }
    if (tid == 0) g_rev_partial[blockIdx.x] = red[0];
}

// ---------------------------------------------------------------------------
// Kernel 6: deterministic final reduction
// ---------------------------------------------------------------------------
__global__ void final_kernel(float* __restrict__ out) {
    __shared__ float red[TPB];
    int t = threadIdx.x;
    float v = g_fwd_partial[t];
    if (t < MRG_BLK) v += g_rev_partial[t];
    red[t] = v;
    __syncthreads();
    #pragma unroll
    for (int s = TPB/2; s > 0; s >>= 1) {
        if (t < s) red[t] += red[t + s];
        __syncthreads();
    }
    if (t == 0) out[0] = red[0];
}

extern "C" void kernel_launch(void* const* d_in, const int* in_sizes, int n_in,
                              void* d_out, int out_size) {
    const float* sv    = (const float*)d_in[0];
    const int*   sf    = (const int*)  d_in[1];
    const float* tv    = (const float*)d_in[2];
    const int*   tf    = (const int*)  d_in[3];
    const float* probs = (const float*)d_in[4];
    const float* r1u   = (const float*)d_in[5];
    const float* r2u   = (const float*)d_in[6];

    const size_t fwd_smem = (size_t)FT * sizeof(float4);   // 64 KB
    cudaFuncSetAttribute(fwd_kernel, cudaFuncAttributeMaxDynamicSharedMemorySize, (int)fwd_smem);

    prep_kernel   <<<NPTS / TPB, TPB>>>(sv, sf, tv, tf, r1u, r2u);
    rev_tgt_kernel<<<256, RTPB>>>();
    fwd_kernel    <<<FWD_BLK, TPB, fwd_smem>>>(probs);
    rev_src_kernel<<<256, RTPB>>>();           // 4th launch -> ncu capture slot
    merge_kernel  <<<MRG_BLK, TPB>>>(probs);
    final_kernel  <<<1, TPB>>>((float*)d_out);
}

// round 5
// speedup vs baseline: 1.7694x; 1.7694x over previous
#include <cuda_runtime.h>

#define FS 4096
#define FT 4096
#define NPTS (FS * 8)            // 32768 sample points
#define NPE  (NPTS + FS)         // + 4096 src barycenters = 36864
#define TPB 256
#define RTPB 128
#define SLICES 4
#define SL 1024                  // candidates per slice
#define CH 16                    // chunk size
#define NCH (SL / CH)            // 64 chunks per slice
#define SRC_PG (NPTS / (RTPB * 2))   // 128 point-groups (256 pts each)
#define TGT_PG (NPE  / (RTPB * 2))   // 144 point-groups
#define MRG_BLK (NPTS / TPB)         // 128
#define FSUM_BLK (FS / TPB)          // 16

typedef unsigned long long u64;

// Scratch (allocation-free: __device__ globals)
__device__ float4 g_src_bc[FS];        // xyz, w = 0.5*|bc|^2 (candidate form)
__device__ float4 g_tgt_bc[FT];        // xyz, w = 0.5*|bc|^2
__device__ float4 g_pts[NPE];          // xyz, w = |p|^2 (full norm)
__device__ float  g_be[SLICES][NPTS][6];
__device__ int    g_bi[SLICES][NPTS][6];
__device__ float  g_mteh[SLICES][NPE];
__device__ float  g_fwd_partial[FSUM_BLK];
__device__ float  g_rev_partial[MRG_BLK];

// ---- packed f32x2 helpers (sm_103a) ---------------------------------------
__device__ __forceinline__ u64 pk2(float a, float b) {
    u64 r; asm("mov.b64 %0,{%1,%2};" : "=l"(r) : "f"(a), "f"(b)); return r;
}
__device__ __forceinline__ u64 fma2(u64 a, u64 b, u64 c) {
    u64 d; asm("fma.rn.f32x2 %0,%1,%2,%3;" : "=l"(d) : "l"(a), "l"(b), "l"(c)); return d;
}
__device__ __forceinline__ void upk2(u64 d, float& x, float& y) {
    asm("mov.b64 {%0,%1},%2;" : "=f"(x), "=f"(y) : "l"(d));
}

// ascending insert, strict < keeps earlier (lower-index) candidate on ties
__device__ __forceinline__ void try_insert(float e, int j, float be[6], int bi[6]) {
    if (e < be[5]) {
        be[5] = e; bi[5] = j;
        #pragma unroll
        for (int k = 5; k > 0; --k) {
            if (be[k] < be[k-1]) {
                float te = be[k]; be[k] = be[k-1]; be[k-1] = te;
                int   ti = bi[k]; bi[k] = bi[k-1]; bi[k-1] = ti;
            }
        }
    }
}

// Pack SL candidates (pair-interleaved) from g[off..off+SL) into smem.
__device__ __forceinline__ void load_packed_slice(ulonglong2* s, const float4* g,
                                                  int off, int tid) {
    for (int t = tid; t < SL/2; t += RTPB) {
        float4 a = g[off + 2*t], b = g[off + 2*t + 1];
        ulonglong2 u0, u1;
        u0.x = pk2(a.x, b.x); u0.y = pk2(a.y, b.y);
        u1.x = pk2(a.z, b.z); u1.y = pk2(a.w, b.w);
        s[2*t]   = u0;
        s[2*t+1] = u1;
    }
}

// ---------------------------------------------------------------------------
// Kernel 1: barycenters + sampled points (+ barycenters-as-points)
// ---------------------------------------------------------------------------
__global__ void prep_kernel(const float* __restrict__ sv, const int* __restrict__ sf,
                            const float* __restrict__ tv, const int* __restrict__ tf,
                            const float* __restrict__ r1u, const float* __restrict__ r2u) {
    int i = blockIdx.x * blockDim.x + threadIdx.x;
    if (i < FS) {
        int a = sf[3*i+0], b = sf[3*i+1], c = sf[3*i+2];
        float x = (sv[3*a+0] + sv[3*b+0] + sv[3*c+0]) * (1.0f/3.0f);
        float y = (sv[3*a+1] + sv[3*b+1] + sv[3*c+1]) * (1.0f/3.0f);
        float z = (sv[3*a+2] + sv[3*b+2] + sv[3*c+2]) * (1.0f/3.0f);
        float n2 = x*x + y*y + z*z;
        g_src_bc[i]      = make_float4(x, y, z, 0.5f*n2);
        g_pts[NPTS + i]  = make_float4(x, y, z, n2);       // fwd loss as a "point"
        int ta = tf[i], tb = tf[FT + i], tc = tf[2*FT + i];
        float tx = (tv[3*ta+0] + tv[3*tb+0] + tv[3*tc+0]) * (1.0f/3.0f);
        float ty = (tv[3*ta+1] + tv[3*tb+1] + tv[3*tc+1]) * (1.0f/3.0f);
        float tz = (tv[3*ta+2] + tv[3*tb+2] + tv[3*tc+2]) * (1.0f/3.0f);
        g_tgt_bc[i] = make_float4(tx, ty, tz, 0.5f*(tx*tx + ty*ty + tz*tz));
    }
    if (i < NPTS) {
        int f = i >> 3;
        int a = sf[3*f+0], b = sf[3*f+1], c = sf[3*f+2];
        float r1 = sqrtf(r1u[i]);
        float r2 = r2u[i];
        float w1 = 1.0f - r1;
        float w2 = r1 * (1.0f - r2);
        float w3 = r1 * r2;
        float x = w1*sv[3*a+0] + w2*sv[3*b+0] + w3*sv[3*c+0];
        float y = w1*sv[3*a+1] + w2*sv[3*b+1] + w3*sv[3*c+1];
        float z = w1*sv[3*a+2] + w2*sv[3*b+2] + w3*sv[3*c+2];
        g_pts[i] = make_float4(x, y, z, x*x + y*y + z*z);
    }
}

// ---------------------------------------------------------------------------
// Kernel 2: target min over one slice — branchless. Covers 36864 points.
// grid = TGT_PG * SLICES : pg = b>>2, slice = b&3
// ---------------------------------------------------------------------------
__global__ void __launch_bounds__(RTPB) rev_tgt_kernel() {
    __shared__ ulonglong2 s_pk[SL];   // 16 KB
    int tid = threadIdx.x;
    int pg  = blockIdx.x >> 2;
    int sl  = blockIdx.x & 3;
    load_packed_slice(s_pk, g_tgt_bc, sl * SL, tid);
    __syncthreads();

    int i0 = pg * 256 + tid;
    int i1 = i0 + 128;
    float4 p0 = g_pts[i0], p1 = g_pts[i1];
    u64 ax = pk2(-p0.x, -p0.x), ay = pk2(-p0.y, -p0.y), az = pk2(-p0.z, -p0.z);
    u64 bx = pk2(-p1.x, -p1.x), by = pk2(-p1.y, -p1.y), bz = pk2(-p1.z, -p1.z);

    float mA0 = 1e30f, mA1 = 1e30f, mB0 = 1e30f, mB1 = 1e30f;
    #pragma unroll 8
    for (int t = 0; t < SL/2; t++) {
        ulonglong2 U = s_pk[2*t], V = s_pk[2*t+1];
        u64 dA = fma2(ax, U.x, fma2(ay, U.y, fma2(az, V.x, V.y)));
        u64 dB = fma2(bx, U.x, fma2(by, U.y, fma2(bz, V.x, V.y)));
        float e0, e1;
        upk2(dA, e0, e1); mA0 = fminf(mA0, e0); mA1 = fminf(mA1, e1);
        upk2(dB, e0, e1); mB0 = fminf(mB0, e0); mB1 = fminf(mB1, e1);
    }
    g_mteh[sl][i0] = fminf(mA0, mA1);
    g_mteh[sl][i1] = fminf(mB0, mB1);
}

// ---------------------------------------------------------------------------
// Kernel 3: source top-6 over one slice — exact two-stage.
// Stage 1: branchless chunk minima (CH=16), keep top-6 chunk mins.
// Stage 2: rescan the 6 selected chunks with full insertion.
// grid = SRC_PG * SLICES : pg = b>>2, slice = b&3
// ---------------------------------------------------------------------------
__global__ void __launch_bounds__(RTPB) rev_src_kernel() {
    __shared__ ulonglong2 s_pk[SL];   // 16 KB
    int tid = threadIdx.x;
    int pg  = blockIdx.x >> 2;
    int sl  = blockIdx.x & 3;
    int jb  = sl * SL;
    load_packed_slice(s_pk, g_src_bc, jb, tid);
    __syncthreads();

    int i0 = pg * 256 + tid;
    int i1 = i0 + 128;
    float4 p0 = g_pts[i0], p1 = g_pts[i1];
    u64 ax = pk2(-p0.x, -p0.x), ay = pk2(-p0.y, -p0.y), az = pk2(-p0.z, -p0.z);
    u64 bx = pk2(-p1.x, -p1.x), by = pk2(-p1.y, -p1.y), bz = pk2(-p1.z, -p1.z);

    // ---- Stage 1: top-6 of chunk minima ----
    float beA[6], beB[6]; int biA[6], biB[6];
    #pragma unroll
    for (int k = 0; k < 6; k++) {
        beA[k] = 1e30f; biA[k] = -1;
        beB[k] = 1e30f; biB[k] = -1;
    }
    for (int c = 0; c < NCH; c++) {
        float mA = 1e30f, mB = 1e30f;
        int base = CH * c;
        #pragma unroll
        for (int t = 0; t < CH/2; t++) {
            ulonglong2 U = s_pk[base + 2*t], V = s_pk[base + 2*t + 1];
            u64 dA = fma2(ax, U.x, fma2(ay, U.y, fma2(az, V.x, V.y)));
            u64 dB = fma2(bx, U.x, fma2(by, U.y, fma2(bz, V.x, V.y)));
            float e0, e1;
            upk2(dA, e0, e1); mA = fminf(mA, fminf(e0, e1));
            upk2(dB, e0, e1); mB = fminf(mB, fminf(e0, e1));
        }
        try_insert(mA, c, beA, biA);
        try_insert(mB, c, beB, biB);
    }

    // ---- Stage 2: rescan selected chunks (ascending chunk id for ties) ----
    int idsA[6], idsB[6];
    #pragma unroll
    for (int k = 0; k < 6; k++) { idsA[k] = biA[k]; idsB[k] = biB[k]; }
    #pragma unroll
    for (int a = 1; a < 6; a++)
        #pragma unroll
        for (int b2 = a; b2 > 0; b2--) {
            if (idsA[b2] < idsA[b2-1]) { int t = idsA[b2]; idsA[b2] = idsA[b2-1]; idsA[b2-1] = t; }
            if (idsB[b2] < idsB[b2-1]) { int t = idsB[b2]; idsB[b2] = idsB[b2-1]; idsB[b2-1] = t; }
        }
    #pragma unroll
    for (int k = 0; k < 6; k++) {
        beA[k] = 1e30f; biA[k] = -1;
        beB[k] = 1e30f; biB[k] = -1;
    }
    #pragma unroll
    for (int k = 0; k < 6; k++) {
        int base = CH * idsA[k];
        #pragma unroll
        for (int t = 0; t < CH/2; t++) {
            ulonglong2 U = s_pk[base + 2*t], V = s_pk[base + 2*t + 1];
            u64 dA = fma2(ax, U.x, fma2(ay, U.y, fma2(az, V.x, V.y)));
            float e0, e1; upk2(dA, e0, e1);
            int j = jb + base + 2*t;
            try_insert(e0, j,     beA, biA);
            try_insert(e1, j + 1, beA, biA);
        }
    }
    #pragma unroll
    for (int k = 0; k < 6; k++) {
        int base = CH * idsB[k];
        #pragma unroll
        for (int t = 0; t < CH/2; t++) {
            ulonglong2 U = s_pk[base + 2*t], V = s_pk[base + 2*t + 1];
            u64 dB = fma2(bx, U.x, fma2(by, U.y, fma2(bz, V.x, V.y)));
            float e0, e1; upk2(dB, e0, e1);
            int j = jb + base + 2*t;
            try_insert(e0, j,     beB, biB);
            try_insert(e1, j + 1, beB, biB);
        }
    }
    #pragma unroll
    for (int k = 0; k < 6; k++) {
        g_be[sl][i0][k] = beA[k];  g_bi[sl][i0][k] = biA[k];
        g_be[sl][i1][k] = beB[k];  g_bi[sl][i1][k] = biB[k];
    }
}

// ---------------------------------------------------------------------------
// Kernel 4: forward loss from extended target-min results
// ---------------------------------------------------------------------------
__global__ void fwd_sum_kernel(const float* __restrict__ probs) {
    int tid = threadIdx.x;
    int f   = blockIdx.x * TPB + tid;
    int i   = NPTS + f;
    float mte = fminf(fminf(g_mteh[0][i], g_mteh[1][i]),
                      fminf(g_mteh[2][i], g_mteh[3][i]));
    float d = fmaxf(fmaf(2.0f, mte, g_pts[i].w), 0.0f);
    float contrib = probs[f] * d;

    __shared__ float red[TPB];
    red[tid] = contrib;
    __syncthreads();
    #pragma unroll
    for (int s = TPB/2; s > 0; s >>= 1) {
        if (tid < s) red[tid] += red[tid + s];
        __syncthreads();
    }
    if (tid == 0) g_fwd_partial[blockIdx.x] = red[0];
}

// ---------------------------------------------------------------------------
// Kernel 5: merge 4 slice lists, self-exclusion, per-point value, reduce.
// ---------------------------------------------------------------------------
__device__ __forceinline__ void merge6(const float* ea, const int* ia,
                                       const float* eb, const int* ib,
                                       float* eo, int* io) {
    int a = 0, b = 0;
    #pragma unroll
    for (int k = 0; k < 6; k++) {
        float va = ea[a], vb = eb[b];
        bool tA = (va <= vb);          // left list = lower indices wins ties
        eo[k] = tA ? va : vb;
        io[k] = tA ? ia[a] : ib[b];
        a += tA ? 1 : 0;
        b += tA ? 0 : 1;
    }
}

__global__ void merge_kernel(const float* __restrict__ probs) {
    int tid = threadIdx.x;
    int i   = blockIdx.x * TPB + tid;
    int sface = i >> 3;

    float e0[6], e1[6], e2[6], e3[6];
    int   j0[6], j1[6], j2[6], j3[6];
    #pragma unroll
    for (int k = 0; k < 6; k++) {
        e0[k] = g_be[0][i][k]; j0[k] = g_bi[0][i][k];
        e1[k] = g_be[1][i][k]; j1[k] = g_bi[1][i][k];
        e2[k] = g_be[2][i][k]; j2[k] = g_bi[2][i][k];
        e3[k] = g_be[3][i][k]; j3[k] = g_bi[3][i][k];
    }
    float m01[6], m23[6], me[6];
    int   i01[6], i23[6], mi[6];
    merge6(e0, j0, e1, j1, m01, i01);
    merge6(e2, j2, e3, j3, m23, i23);
    merge6(m01, i01, m23, i23, me, mi);

    float pw = g_pts[i].w;
    int selfpos = 6;
    #pragma unroll
    for (int k = 0; k < 6; k++) if (mi[k] == sface) selfpos = k;
    float s5 = 0.0f;
    #pragma unroll
    for (int k = 0; k < 6; k++) {
        bool inc = (k != selfpos) && (k < 5 || selfpos <= 5);
        if (inc) {
            float d = fmaxf(fmaf(2.0f, me[k], pw), 0.0f);
            s5 += probs[mi[k]] * d;
        }
    }
    float mte = fminf(fminf(g_mteh[0][i], g_mteh[1][i]),
                      fminf(g_mteh[2][i], g_mteh[3][i]));
    float pp   = probs[sface];
    float mind = fmaxf(fmaf(2.0f, mte, pw), 0.0f);
    float val  = fmaf(pp, mind, (1.0f - pp) * (s5 * 0.2f));

    __shared__ float red[TPB];
    red[tid] = val;
    __syncthreads();
    #pragma unroll
    for (int s = TPB/2; s > 0; s >>= 1) {
        if (tid < s) red[tid] += red[tid + s];
        __syncthreads();
    }
    if (tid == 0) g_rev_partial[blockIdx.x] = red[0];
}

// ---------------------------------------------------------------------------
// Kernel 6: deterministic final reduction
// ---------------------------------------------------------------------------
__global__ void final_kernel(float* __restrict__ out) {
    __shared__ float red[TPB];
    int t = threadIdx.x;
    float v = 0.0f;
    if (t < MRG_BLK)  v += g_rev_partial[t];
    if (t < FSUM_BLK) v += g_fwd_partial[t];
    red[t] = v;
    __syncthreads();
    #pragma unroll
    for (int s = TPB/2; s > 0; s >>= 1) {
        if (t < s) red[t] += red[t + s];
        __syncthreads();
    }
    if (t == 0) out[0] = red[0];
}

extern "C" void kernel_launch(void* const* d_in, const int* in_sizes, int n_in,
                              void* d_out, int out_size) {
    const float* sv    = (const float*)d_in[0];
    const int*   sf    = (const int*)  d_in[1];
    const float* tv    = (const float*)d_in[2];
    const int*   tf    = (const int*)  d_in[3];
    const float* probs = (const float*)d_in[4];
    const float* r1u   = (const float*)d_in[5];
    const float* r2u   = (const float*)d_in[6];

    prep_kernel   <<<NPTS / TPB, TPB>>>(sv, sf, tv, tf, r1u, r2u);
    rev_tgt_kernel<<<TGT_PG * SLICES, RTPB>>>();   // 576 blocks
    fwd_sum_kernel<<<FSUM_BLK, TPB>>>(probs);
    rev_src_kernel<<<SRC_PG * SLICES, RTPB>>>();   // 512 blocks (4th: ncu slot)
    merge_kernel  <<<MRG_BLK, TPB>>>(probs);
    final_kernel  <<<1, TPB>>>((float*)d_out);
}

// round 6
// speedup vs baseline: 1.8883x; 1.0672x over previous
#include <cuda_runtime.h>

#define FS 4096
#define FT 4096
#define NPTS (FS * 8)            // 32768 sample points
#define NPE  (NPTS + FS)         // + 4096 src barycenters = 36864
#define TPB 256
#define RTPB 128
#define SLICES 8
#define SL 512                   // candidates per slice
#define CH 8                     // chunk size
#define NCH (SL / CH)            // 64 chunks per slice
#define SRC_PG (NPTS / (RTPB * 2))   // 128 point-groups (256 pts each)
#define TGT_PG (NPE  / (RTPB * 2))   // 144 point-groups
#define MRG_BLK (NPTS / TPB)         // 128
#define FSUM_BLK (FS / TPB)          // 16

typedef unsigned long long u64;

// Scratch (allocation-free: __device__ globals)
__device__ float4 g_src_bc[FS];        // xyz, w = 0.5*|bc|^2 (candidate form)
__device__ float4 g_tgt_bc[FT];        // xyz, w = 0.5*|bc|^2
__device__ float4 g_pts[NPE];          // xyz, w = |p|^2 (full norm)
__device__ float  g_be[SLICES][NPTS][6];
__device__ int    g_bi[SLICES][NPTS][6];
__device__ float  g_mteh[SLICES][NPE];
__device__ float  g_fwd_partial[FSUM_BLK];
__device__ float  g_rev_partial[MRG_BLK];

// ---- packed f32x2 helpers (sm_103a) ---------------------------------------
__device__ __forceinline__ u64 pk2(float a, float b) {
    u64 r; asm("mov.b64 %0,{%1,%2};" : "=l"(r) : "f"(a), "f"(b)); return r;
}
__device__ __forceinline__ u64 fma2(u64 a, u64 b, u64 c) {
    u64 d; asm("fma.rn.f32x2 %0,%1,%2,%3;" : "=l"(d) : "l"(a), "l"(b), "l"(c)); return d;
}
__device__ __forceinline__ void upk2(u64 d, float& x, float& y) {
    asm("mov.b64 {%0,%1},%2;" : "=f"(x), "=f"(y) : "l"(d));
}

// ascending insert, strict < keeps earlier (lower-index) candidate on ties
__device__ __forceinline__ void try_insert(float e, int j, float be[6], int bi[6]) {
    if (e < be[5]) {
        be[5] = e; bi[5] = j;
        #pragma unroll
        for (int k = 5; k > 0; --k) {
            if (be[k] < be[k-1]) {
                float te = be[k]; be[k] = be[k-1]; be[k-1] = te;
                int   ti = bi[k]; bi[k] = bi[k-1]; bi[k-1] = ti;
            }
        }
    }
}

// Pack SL candidates (pair-interleaved) from g[off..off+SL) into smem.
__device__ __forceinline__ void load_packed_slice(ulonglong2* s, const float4* g,
                                                  int off, int tid) {
    for (int t = tid; t < SL/2; t += RTPB) {
        float4 a = g[off + 2*t], b = g[off + 2*t + 1];
        ulonglong2 u0, u1;
        u0.x = pk2(a.x, b.x); u0.y = pk2(a.y, b.y);
        u1.x = pk2(a.z, b.z); u1.y = pk2(a.w, b.w);
        s[2*t]   = u0;
        s[2*t+1] = u1;
    }
}

// ---------------------------------------------------------------------------
// Kernel 1: barycenters + sampled points (+ barycenters-as-points)
// ---------------------------------------------------------------------------
__global__ void prep_kernel(const float* __restrict__ sv, const int* __restrict__ sf,
                            const float* __restrict__ tv, const int* __restrict__ tf,
                            const float* __restrict__ r1u, const float* __restrict__ r2u) {
    int i = blockIdx.x * blockDim.x + threadIdx.x;
    if (i < FS) {
        int a = sf[3*i+0], b = sf[3*i+1], c = sf[3*i+2];
        float x = (sv[3*a+0] + sv[3*b+0] + sv[3*c+0]) * (1.0f/3.0f);
        float y = (sv[3*a+1] + sv[3*b+1] + sv[3*c+1]) * (1.0f/3.0f);
        float z = (sv[3*a+2] + sv[3*b+2] + sv[3*c+2]) * (1.0f/3.0f);
        float n2 = x*x + y*y + z*z;
        g_src_bc[i]      = make_float4(x, y, z, 0.5f*n2);
        g_pts[NPTS + i]  = make_float4(x, y, z, n2);       // fwd loss as a "point"
        int ta = tf[i], tb = tf[FT + i], tc = tf[2*FT + i];
        float tx = (tv[3*ta+0] + tv[3*tb+0] + tv[3*tc+0]) * (1.0f/3.0f);
        float ty = (tv[3*ta+1] + tv[3*tb+1] + tv[3*tc+1]) * (1.0f/3.0f);
        float tz = (tv[3*ta+2] + tv[3*tb+2] + tv[3*tc+2]) * (1.0f/3.0f);
        g_tgt_bc[i] = make_float4(tx, ty, tz, 0.5f*(tx*tx + ty*ty + tz*tz));
    }
    if (i < NPTS) {
        int f = i >> 3;
        int a = sf[3*f+0], b = sf[3*f+1], c = sf[3*f+2];
        float r1 = sqrtf(r1u[i]);
        float r2 = r2u[i];
        float w1 = 1.0f - r1;
        float w2 = r1 * (1.0f - r2);
        float w3 = r1 * r2;
        float x = w1*sv[3*a+0] + w2*sv[3*b+0] + w3*sv[3*c+0];
        float y = w1*sv[3*a+1] + w2*sv[3*b+1] + w3*sv[3*c+1];
        float z = w1*sv[3*a+2] + w2*sv[3*b+2] + w3*sv[3*c+2];
        g_pts[i] = make_float4(x, y, z, x*x + y*y + z*z);
    }
}

// ---------------------------------------------------------------------------
// Kernel 2: target min over one slice — branchless. Covers 36864 points.
// grid = TGT_PG * SLICES : pg = b>>3, slice = b&7
// ---------------------------------------------------------------------------
__global__ void __launch_bounds__(RTPB) rev_tgt_kernel() {
    __shared__ ulonglong2 s_pk[SL];   // 8 KB
    int tid = threadIdx.x;
    int pg  = blockIdx.x >> 3;
    int sl  = blockIdx.x & 7;
    load_packed_slice(s_pk, g_tgt_bc, sl * SL, tid);
    __syncthreads();

    int i0 = pg * 256 + tid;
    int i1 = i0 + 128;
    float4 p0 = g_pts[i0], p1 = g_pts[i1];
    u64 ax = pk2(-p0.x, -p0.x), ay = pk2(-p0.y, -p0.y), az = pk2(-p0.z, -p0.z);
    u64 bx = pk2(-p1.x, -p1.x), by = pk2(-p1.y, -p1.y), bz = pk2(-p1.z, -p1.z);

    float mA0 = 1e30f, mA1 = 1e30f, mB0 = 1e30f, mB1 = 1e30f;
    #pragma unroll 8
    for (int t = 0; t < SL/2; t++) {
        ulonglong2 U = s_pk[2*t], V = s_pk[2*t+1];
        u64 dA = fma2(ax, U.x, fma2(ay, U.y, fma2(az, V.x, V.y)));
        u64 dB = fma2(bx, U.x, fma2(by, U.y, fma2(bz, V.x, V.y)));
        float e0, e1;
        upk2(dA, e0, e1); mA0 = fminf(mA0, e0); mA1 = fminf(mA1, e1);
        upk2(dB, e0, e1); mB0 = fminf(mB0, e0); mB1 = fminf(mB1, e1);
    }
    g_mteh[sl][i0] = fminf(mA0, mA1);
    g_mteh[sl][i1] = fminf(mB0, mB1);
}

// ---------------------------------------------------------------------------
// Kernel 3: source top-6 over one slice — exact two-stage.
// Stage 1: branchless chunk minima (CH=8), keep top-6 chunk mins.
// Stage 2: rescan the 6 selected chunks with full insertion.
// grid = SRC_PG * SLICES : pg = b>>3, slice = b&7
// ---------------------------------------------------------------------------
__global__ void __launch_bounds__(RTPB) rev_src_kernel() {
    __shared__ ulonglong2 s_pk[SL];   // 8 KB
    int tid = threadIdx.x;
    int pg  = blockIdx.x >> 3;
    int sl  = blockIdx.x & 7;
    int jb  = sl * SL;
    load_packed_slice(s_pk, g_src_bc, jb, tid);
    __syncthreads();

    int i0 = pg * 256 + tid;
    int i1 = i0 + 128;
    float4 p0 = g_pts[i0], p1 = g_pts[i1];
    u64 ax = pk2(-p0.x, -p0.x), ay = pk2(-p0.y, -p0.y), az = pk2(-p0.z, -p0.z);
    u64 bx = pk2(-p1.x, -p1.x), by = pk2(-p1.y, -p1.y), bz = pk2(-p1.z, -p1.z);

    // ---- Stage 1: top-6 of chunk minima ----
    float beA[6], beB[6]; int biA[6], biB[6];
    #pragma unroll
    for (int k = 0; k < 6; k++) {
        beA[k] = 1e30f; biA[k] = -1;
        beB[k] = 1e30f; biB[k] = -1;
    }
    for (int c = 0; c < NCH; c++) {
        float mA = 1e30f, mB = 1e30f;
        int base = CH * c;
        #pragma unroll
        for (int t = 0; t < CH/2; t++) {
            ulonglong2 U = s_pk[base + 2*t], V = s_pk[base + 2*t + 1];
            u64 dA = fma2(ax, U.x, fma2(ay, U.y, fma2(az, V.x, V.y)));
            u64 dB = fma2(bx, U.x, fma2(by, U.y, fma2(bz, V.x, V.y)));
            float e0, e1;
            upk2(dA, e0, e1); mA = fminf(mA, fminf(e0, e1));
            upk2(dB, e0, e1); mB = fminf(mB, fminf(e0, e1));
        }
        try_insert(mA, c, beA, biA);
        try_insert(mB, c, beB, biB);
    }

    // ---- Stage 2: rescan selected chunks (ascending chunk id for ties) ----
    int idsA[6], idsB[6];
    #pragma unroll
    for (int k = 0; k < 6; k++) { idsA[k] = biA[k]; idsB[k] = biB[k]; }
    #pragma unroll
    for (int a = 1; a < 6; a++)
        #pragma unroll
        for (int b2 = a; b2 > 0; b2--) {
            if (idsA[b2] < idsA[b2-1]) { int t = idsA[b2]; idsA[b2] = idsA[b2-1]; idsA[b2-1] = t; }
            if (idsB[b2] < idsB[b2-1]) { int t = idsB[b2]; idsB[b2] = idsB[b2-1]; idsB[b2-1] = t; }
        }
    #pragma unroll
    for (int k = 0; k < 6; k++) {
        beA[k] = 1e30f; biA[k] = -1;
        beB[k] = 1e30f; biB[k] = -1;
    }
    #pragma unroll
    for (int k = 0; k < 6; k++) {
        int base = CH * idsA[k];
        #pragma unroll
        for (int t = 0; t < CH/2; t++) {
            ulonglong2 U = s_pk[base + 2*t], V = s_pk[base + 2*t + 1];
            u64 dA = fma2(ax, U.x, fma2(ay, U.y, fma2(az, V.x, V.y)));
            float e0, e1; upk2(dA, e0, e1);
            int j = jb + base + 2*t;
            try_insert(e0, j,     beA, biA);
            try_insert(e1, j + 1, beA, biA);
        }
    }
    #pragma unroll
    for (int k = 0; k < 6; k++) {
        int base = CH * idsB[k];
        #pragma unroll
        for (int t = 0; t < CH/2; t++) {
            ulonglong2 U = s_pk[base + 2*t], V = s_pk[base + 2*t + 1];
            u64 dB = fma2(bx, U.x, fma2(by, U.y, fma2(bz, V.x, V.y)));
            float e0, e1; upk2(dB, e0, e1);
            int j = jb + base + 2*t;
            try_insert(e0, j,     beB, biB);
            try_insert(e1, j + 1, beB, biB);
        }
    }
    #pragma unroll
    for (int k = 0; k < 6; k++) {
        g_be[sl][i0][k] = beA[k];  g_bi[sl][i0][k] = biA[k];
        g_be[sl][i1][k] = beB[k];  g_bi[sl][i1][k] = biB[k];
    }
}

// ---------------------------------------------------------------------------
// Kernel 4: forward loss from extended target-min results
// ---------------------------------------------------------------------------
__global__ void fwd_sum_kernel(const float* __restrict__ probs) {
    int tid = threadIdx.x;
    int f   = blockIdx.x * TPB + tid;
    int i   = NPTS + f;
    float mte = 1e30f;
    #pragma unroll
    for (int s = 0; s < SLICES; s++) mte = fminf(mte, g_mteh[s][i]);
    float d = fmaxf(fmaf(2.0f, mte, g_pts[i].w), 0.0f);
    float contrib = probs[f] * d;

    __shared__ float red[TPB];
    red[tid] = contrib;
    __syncthreads();
    #pragma unroll
    for (int s = TPB/2; s > 0; s >>= 1) {
        if (tid < s) red[tid] += red[tid + s];
        __syncthreads();
    }
    if (tid == 0) g_fwd_partial[blockIdx.x] = red[0];
}

// ---------------------------------------------------------------------------
// Kernel 5: merge 8 slice lists, self-exclusion, per-point value, reduce.
// ---------------------------------------------------------------------------
__device__ __forceinline__ void merge6(const float* ea, const int* ia,
                                       const float* eb, const int* ib,
                                       float* eo, int* io) {
    int a = 0, b = 0;
    #pragma unroll
    for (int k = 0; k < 6; k++) {
        float va = ea[a], vb = eb[b];
        bool tA = (va <= vb);          // left list = lower indices wins ties
        eo[k] = tA ? va : vb;
        io[k] = tA ? ia[a] : ib[b];
        a += tA ? 1 : 0;
        b += tA ? 0 : 1;
    }
}

__global__ void merge_kernel(const float* __restrict__ probs) {
    int tid = threadIdx.x;
    int i   = blockIdx.x * TPB + tid;
    int sface = i >> 3;

    float me[6]; int mi[6];
    #pragma unroll
    for (int k = 0; k < 6; k++) { me[k] = g_be[0][i][k]; mi[k] = g_bi[0][i][k]; }
    #pragma unroll
    for (int s = 1; s < SLICES; s++) {
        float eb[6], tmp[6]; int ib[6], tmpi[6];
        #pragma unroll
        for (int k = 0; k < 6; k++) { eb[k] = g_be[s][i][k]; ib[k] = g_bi[s][i][k]; }
        merge6(me, mi, eb, ib, tmp, tmpi);
        #pragma unroll
        for (int k = 0; k < 6; k++) { me[k] = tmp[k]; mi[k] = tmpi[k]; }
    }

    float pw = g_pts[i].w;
    int selfpos = 6;
    #pragma unroll
    for (int k = 0; k < 6; k++) if (mi[k] == sface) selfpos = k;
    float s5 = 0.0f;
    #pragma unroll
    for (int k = 0; k < 6; k++) {
        bool inc = (k != selfpos) && (k < 5 || selfpos <= 5);
        if (inc) {
            float d = fmaxf(fmaf(2.0f, me[k], pw), 0.0f);
            s5 += probs[mi[k]] * d;
        }
    }
    float mte = 1e30f;
    #pragma unroll
    for (int s = 0; s < SLICES; s++) mte = fminf(mte, g_mteh[s][i]);
    float pp   = probs[sface];
    float mind = fmaxf(fmaf(2.0f, mte, pw), 0.0f);
    float val  = fmaf(pp, mind, (1.0f - pp) * (s5 * 0.2f));

    __shared__ float red[TPB];
    red[tid] = val;
    __syncthreads();
    #pragma unroll
    for (int s = TPB/2; s > 0; s >>= 1) {
        if (tid < s) red[tid] += red[tid + s];
        __syncthreads();
    }
    if (tid == 0) g_rev_partial[blockIdx.x] = red[0];
}

// ---------------------------------------------------------------------------
// Kernel 6: deterministic final reduction
// ---------------------------------------------------------------------------
__global__ void final_kernel(float* __restrict__ out) {
    __shared__ float red[TPB];
    int t = threadIdx.x;
    float v = 0.0f;
    if (t < MRG_BLK)  v += g_rev_partial[t];
    if (t < FSUM_BLK) v += g_fwd_partial[t];
    red[t] = v;
    __syncthreads();
    #pragma unroll
    for (int s = TPB/2; s > 0; s >>= 1) {
        if (t < s) red[t] += red[t + s];
        __syncthreads();
    }
    if (t == 0) out[0] = red[0];
}

extern "C" void kernel_launch(void* const* d_in, const int* in_sizes, int n_in,
                              void* d_out, int out_size) {
    const float* sv    = (const float*)d_in[0];
    const int*   sf    = (const int*)  d_in[1];
    const float* tv    = (const float*)d_in[2];
    const int*   tf    = (const int*)  d_in[3];
    const float* probs = (const float*)d_in[4];
    const float* r1u   = (const float*)d_in[5];
    const float* r2u   = (const float*)d_in[6];

    prep_kernel   <<<NPTS / TPB, TPB>>>(sv, sf, tv, tf, r1u, r2u);
    rev_tgt_kernel<<<TGT_PG * SLICES, RTPB>>>();   // 1152 blocks
    fwd_sum_kernel<<<FSUM_BLK, TPB>>>(probs);
    rev_src_kernel<<<SRC_PG * SLICES, RTPB>>>();   // 1024 blocks (4th: ncu slot)
    merge_kernel  <<<MRG_BLK, TPB>>>(probs);
    final_kernel  <<<1, TPB>>>((float*)d_out);
}